// round 1
// baseline (speedup 1.0000x reference)
#include <cuda_runtime.h>
#include <cuda_bf16.h>
#include <math.h>

// Problem constants (fixed by setup_inputs)
#define NQ    128
#define NK    2048
#define SEQ   32
#define ZD    24      // d5 / seq_len
#define D5    768
#define QB    8       // q rows per block
#define KB    16      // k rows per block
#define NTHR  256

typedef unsigned long long ull;

__device__ __forceinline__ ull fma2(ull a, ull b, ull c) {
    ull d;
    asm("fma.rn.f32x2 %0, %1, %2, %3;" : "=l"(d) : "l"(a), "l"(b), "l"(c));
    return d;
}

__device__ __forceinline__ float hadd2(ull a) {
    float lo, hi;
    asm("mov.b64 {%0, %1}, %2;" : "=f"(lo), "=f"(hi) : "l"(a));
    return lo + hi;
}

// Order-preserving float<->int mapping so __reduce_max_sync (int) computes float max.
__device__ __forceinline__ int f2ord(float x) {
    int i = __float_as_int(x);
    return (i < 0) ? (i ^ 0x7FFFFFFF) : i;
}
__device__ __forceinline__ float ord2f(int i) {
    return __int_as_float((i < 0) ? (i ^ 0x7FFFFFFF) : i);
}

extern __shared__ float4 smem4[];
// Layout:
//   sQ: QB * 192 float4   — Q tile, row-major as in gmem: [q_local][t*6 + d4]
//   sK: KB * 192 float4   — K tile, transposed: [k_local][d4][s]  (s contiguous -> conflict-free)

__global__ __launch_bounds__(NTHR, 2)
void matcher_kernel(const float* __restrict__ tgt,
                    const float* __restrict__ mem,
                    float* __restrict__ out)
{
    float4* sQ = smem4;                  // QB*192
    float4* sK = smem4 + QB * 192;       // KB*192

    const int q0  = blockIdx.y * QB;
    const int k0  = blockIdx.x * KB;
    const int tid = threadIdx.x;

    // Load Q tile (contiguous rows)
    #pragma unroll 2
    for (int e = tid; e < QB * 192; e += NTHR) {
        int qi = e / 192, r = e % 192;
        sQ[e] = reinterpret_cast<const float4*>(tgt + (q0 + qi) * D5)[r];
    }
    // Load K tile, transposed to [k][d4][s]
    #pragma unroll 2
    for (int e = tid; e < KB * 192; e += NTHR) {
        int ki = e / 192, r = e % 192;
        int s = r / 6, d4 = r % 6;
        sK[(ki * 6 + d4) * 32 + s] =
            reinterpret_cast<const float4*>(mem + (k0 + ki) * D5 + s * ZD)[d4];
    }
    __syncthreads();

    const int lane = tid & 31;
    const int warp = tid >> 5;           // warp w -> q_local = w  (QB == 8 warps)
    const ulonglong2* qbase =
        reinterpret_cast<const ulonglong2*>(sQ + warp * 192);
    const ulonglong2* kbase = reinterpret_cast<const ulonglong2*>(sK);
    const float NEG_INF = __int_as_float(0xff800000);

    for (int kk = 0; kk < KB; kk += 2) {
        // Lane `lane` holds K rows s=lane for k_local = kk and kk+1 (12 f32x2 each)
        ull kr[24];
        #pragma unroll
        for (int j = 0; j < 2; ++j) {
            #pragma unroll
            for (int d4 = 0; d4 < 6; ++d4) {
                ulonglong2 v = kbase[((kk + j) * 6 + d4) * 32 + lane];
                kr[j * 12 + d4 * 2]     = v.x;
                kr[j * 12 + d4 * 2 + 1] = v.y;
            }
        }

        float smax0 = NEG_INF, smax1 = NEG_INF;   // max over t, per s=lane
        float tsum0 = 0.f,     tsum1 = 0.f;       // sum over t of (max over s)

        #pragma unroll
        for (int t = 0; t < SEQ; ++t) {
            ull acc0 = 0ull, acc1 = 0ull;         // f32x2 {0,0}
            #pragma unroll
            for (int d4 = 0; d4 < 6; ++d4) {
                ulonglong2 qv = qbase[t * 6 + d4];          // broadcast LDS.128
                acc0 = fma2(kr[d4 * 2],       qv.x, acc0);
                acc1 = fma2(kr[12 + d4 * 2],  qv.x, acc1);
                acc0 = fma2(kr[d4 * 2 + 1],   qv.y, acc0);
                acc1 = fma2(kr[12 + d4 * 2 + 1], qv.y, acc1);
            }
            float v0 = hadd2(acc0);
            float v1 = hadd2(acc1);
            smax0 = fmaxf(smax0, v0);
            smax1 = fmaxf(smax1, v1);
            tsum0 += ord2f(__reduce_max_sync(0xffffffffu, f2ord(v0)));
            tsum1 += ord2f(__reduce_max_sync(0xffffffffu, f2ord(v1)));
        }

        // Warp-sum of per-s maxima
        float s0 = smax0, s1 = smax1;
        #pragma unroll
        for (int o = 16; o; o >>= 1) {
            s0 += __shfl_xor_sync(0xffffffffu, s0, o);
            s1 += __shfl_xor_sync(0xffffffffu, s1, o);
        }

        if (lane == 0) {
            float m0 = (tsum0 + s0) * (1.0f / 64.0f);
            float m1 = (tsum1 + s1) * (1.0f / 64.0f);
            float r0 = 1.0f / (1.0f + expf(-m0));
            float r1 = 1.0f / (1.0f + expf(-m1));
            int q = q0 + warp;
            long long base = (long long)q * NK + k0 + kk;
            out[base]     = r0;
            out[base + 1] = r1;
            out[(long long)NQ * NK + base]     = r0;
            out[(long long)NQ * NK + base + 1] = r1;
        }
    }
}

extern "C" void kernel_launch(void* const* d_in, const int* in_sizes, int n_in,
                              void* d_out, int out_size)
{
    const float* tgt = (const float*)d_in[0];   // [128, 768]
    const float* mem = (const float*)d_in[1];   // [2048, 768]
    float* out = (float*)d_out;                 // [2, 128, 2048]
    (void)in_sizes; (void)n_in; (void)out_size;

    const int smem_bytes = (QB + KB) * 192 * (int)sizeof(float4);  // 73728
    cudaFuncSetAttribute(matcher_kernel,
                         cudaFuncAttributeMaxDynamicSharedMemorySize, smem_bytes);

    dim3 grid(NK / KB, NQ / QB);   // (128, 16)
    matcher_kernel<<<grid, NTHR, smem_bytes>>>(tgt, mem, out);
}

// round 2
// speedup vs baseline: 1.0898x; 1.0898x over previous
#include <cuda_runtime.h>
#include <cuda_bf16.h>
#include <math.h>

#define NQ    128
#define NK    2048
#define SEQ   32
#define ZD    24
#define D5    768
#define QB    8
#define KB    16
#define NTHR  256

#define BIAS  128.0f
// f32x2 accumulator init: lo half = BIAS, hi half = 0  -> v = lo+hi includes bias for free
#define ACC_INIT 0x0000000043000000ULL

typedef unsigned long long ull;

__device__ __forceinline__ ull fma2(ull a, ull b, ull c) {
    ull d;
    asm("fma.rn.f32x2 %0, %1, %2, %3;" : "=l"(d) : "l"(a), "l"(b), "l"(c));
    return d;
}

__device__ __forceinline__ float hadd2(ull a) {
    float lo, hi;
    asm("mov.b64 {%0, %1}, %2;" : "=f"(lo), "=f"(hi) : "l"(a));
    return lo + hi;
}

extern __shared__ float4 smem4[];
// sQ: QB * 192 float4  — Q tile row-major [q_local][t*6 + d4]
// sK: KB * 192 float4  — K tile transposed [k_local][d4][s]

__global__ __launch_bounds__(NTHR, 2)
void matcher_kernel(const float* __restrict__ tgt,
                    const float* __restrict__ mem,
                    float* __restrict__ out)
{
    float4* sQ = smem4;
    float4* sK = smem4 + QB * 192;

    const int q0  = blockIdx.y * QB;
    const int k0  = blockIdx.x * KB;
    const int tid = threadIdx.x;

    #pragma unroll 2
    for (int e = tid; e < QB * 192; e += NTHR) {
        int qi = e / 192, r = e % 192;
        sQ[e] = reinterpret_cast<const float4*>(tgt + (q0 + qi) * D5)[r];
    }
    #pragma unroll 2
    for (int e = tid; e < KB * 192; e += NTHR) {
        int ki = e / 192, r = e % 192;
        int s = r / 6, d4 = r % 6;
        sK[(ki * 6 + d4) * 32 + s] =
            reinterpret_cast<const float4*>(mem + (k0 + ki) * D5 + s * ZD)[d4];
    }
    __syncthreads();

    const int lane = tid & 31;
    const int warp = tid >> 5;
    const ulonglong2* qbase =
        reinterpret_cast<const ulonglong2*>(sQ + warp * 192);
    const ulonglong2* kbase = reinterpret_cast<const ulonglong2*>(sK);

    for (int kk = 0; kk < KB; kk += 2) {
        // Lane `lane` owns K rows s=lane for k_local = kk, kk+1
        ull kr[24];
        #pragma unroll
        for (int j = 0; j < 2; ++j) {
            #pragma unroll
            for (int d4 = 0; d4 < 6; ++d4) {
                ulonglong2 v = kbase[((kk + j) * 6 + d4) * 32 + lane];
                kr[j * 12 + d4 * 2]     = v.x;
                kr[j * 12 + d4 * 2 + 1] = v.y;
            }
        }

        // Biased scores are all positive floats -> u32 compare == float compare.
        unsigned smax0 = 0u, smax1 = 0u;   // max over t, per s=lane (biased bits)
        float tsum0 = 0.f, tsum1 = 0.f;    // sum over t of (max over s), biased

        #pragma unroll
        for (int t = 0; t < SEQ; ++t) {
            ull acc0 = ACC_INIT, acc1 = ACC_INIT;
            #pragma unroll
            for (int d4 = 0; d4 < 6; ++d4) {
                ulonglong2 qv = qbase[t * 6 + d4];       // broadcast LDS.128
                acc0 = fma2(kr[d4 * 2],          qv.x, acc0);
                acc1 = fma2(kr[12 + d4 * 2],     qv.x, acc1);
                acc0 = fma2(kr[d4 * 2 + 1],      qv.y, acc0);
                acc1 = fma2(kr[12 + d4 * 2 + 1], qv.y, acc1);
            }
            unsigned b0 = __float_as_uint(hadd2(acc0));  // biased, positive
            unsigned b1 = __float_as_uint(hadd2(acc1));
            smax0 = max(smax0, b0);                       // IMNMX.U32 (alu pipe)
            smax1 = max(smax1, b1);
            tsum0 += __uint_as_float(__reduce_max_sync(0xffffffffu, b0));
            tsum1 += __uint_as_float(__reduce_max_sync(0xffffffffu, b1));
        }

        float s0 = __uint_as_float(smax0);
        float s1 = __uint_as_float(smax1);
        #pragma unroll
        for (int o = 16; o; o >>= 1) {
            s0 += __shfl_xor_sync(0xffffffffu, s0, o);
            s1 += __shfl_xor_sync(0xffffffffu, s1, o);
        }

        if (lane == 0) {
            float m0 = (tsum0 + s0) * (1.0f / 64.0f) - BIAS;
            float m1 = (tsum1 + s1) * (1.0f / 64.0f) - BIAS;
            float r0 = 1.0f / (1.0f + expf(-m0));
            float r1 = 1.0f / (1.0f + expf(-m1));
            int q = q0 + warp;
            long long base = (long long)q * NK + k0 + kk;
            out[base]     = r0;
            out[base + 1] = r1;
            out[(long long)NQ * NK + base]     = r0;
            out[(long long)NQ * NK + base + 1] = r1;
        }
    }
}

extern "C" void kernel_launch(void* const* d_in, const int* in_sizes, int n_in,
                              void* d_out, int out_size)
{
    const float* tgt = (const float*)d_in[0];
    const float* mem = (const float*)d_in[1];
    float* out = (float*)d_out;
    (void)in_sizes; (void)n_in; (void)out_size;

    const int smem_bytes = (QB + KB) * 192 * (int)sizeof(float4);
    cudaFuncSetAttribute(matcher_kernel,
                         cudaFuncAttributeMaxDynamicSharedMemorySize, smem_bytes);

    dim3 grid(NK / KB, NQ / QB);
    matcher_kernel<<<grid, NTHR, smem_bytes>>>(tgt, mem, out);
}

// round 4
// speedup vs baseline: 3.0223x; 2.7733x over previous
#include <cuda_runtime.h>
#include <cstdint>

#define NQ     128
#define NK     2048
#define D5     768
#define SEQ    32
#define ZD     24
#define NTHR   256
#define KCHUNK 128              // k columns per CTA
#define NB     16               // k rows staged per batch
#define NBATCH (KCHUNK / NB)

// per-buffer: NB * 3 ksteps * 32 s * 4 gc  float2 (tf32-bit pairs)
#define BUF_F2 (NB * 3 * 32 * 4)      // 6144
#define SMEM_BYTES (2 * BUF_F2 * 8)   // 98304

typedef unsigned long long ull;

__device__ __forceinline__ uint32_t cvt_tf32(float f) {
    uint32_t r; asm("cvt.rna.tf32.f32 %0, %1;" : "=r"(r) : "f"(f)); return r;
}

__device__ __forceinline__ void mma8(float* c, const uint32_t* a, ull b) {
    uint32_t b0 = (uint32_t)b, b1 = (uint32_t)(b >> 32);
    asm volatile(
        "mma.sync.aligned.m16n8k8.row.col.f32.tf32.tf32.f32 "
        "{%0,%1,%2,%3}, {%4,%5,%6,%7}, {%8,%9}, {%0,%1,%2,%3};"
        : "+f"(c[0]), "+f"(c[1]), "+f"(c[2]), "+f"(c[3])
        : "r"(a[0]), "r"(a[1]), "r"(a[2]), "r"(a[3]), "r"(b0), "r"(b1));
}

// Stage NB k-rows of `memory` into smem, zipped for direct B-fragment LDS.64:
//   buf[(kk*3+ks)*32 + s][gc] = float2(tf32(mem[s*24 + ks*8 + gc]), tf32(mem[... + gc + 4]))
__device__ __forceinline__ void stage(ull* __restrict__ buf,
                                      const float* __restrict__ kbase, int tid) {
    #pragma unroll
    for (int i = 0; i < 6; ++i) {
        int e  = tid + i * NTHR;          // 0..1535
        int kk = e / 96, rem = e % 96;
        int ks = rem >> 5, s = rem & 31;
        const float* p = kbase + kk * D5 + s * ZD + ks * 8;
        float4 A4 = *reinterpret_cast<const float4*>(p);
        float4 B4 = *reinterpret_cast<const float4*>(p + 4);
        ull p0 = (ull)cvt_tf32(A4.x) | ((ull)cvt_tf32(B4.x) << 32);
        ull p1 = (ull)cvt_tf32(A4.y) | ((ull)cvt_tf32(B4.y) << 32);
        ull p2 = (ull)cvt_tf32(A4.z) | ((ull)cvt_tf32(B4.z) << 32);
        ull p3 = (ull)cvt_tf32(A4.w) | ((ull)cvt_tf32(B4.w) << 32);
        ulonglong2* dst = reinterpret_cast<ulonglong2*>(buf + (size_t)e * 4);
        dst[0] = make_ulonglong2(p0, p1);
        dst[1] = make_ulonglong2(p2, p3);
    }
}

extern __shared__ ull sbuf[];   // 2 buffers of BUF_F2

__global__ __launch_bounds__(NTHR, 2)
void matcher_hmma(const float* __restrict__ tgt,
                  const float* __restrict__ mem,
                  float* __restrict__ out)
{
    const int tid  = threadIdx.x;
    const int warp = tid >> 5;
    const int lane = tid & 31;
    const int gr   = lane >> 2;          // 0..7
    const int gc   = lane & 3;           // 0..3

    const int q0 = (blockIdx.x >> 4) * 8;
    const int k0 = (blockIdx.x & 15) * KCHUNK;
    const int q  = q0 + warp;

    // ---- A fragments (held in regs for the whole kernel): [mi][ks][4] ----
    uint32_t afr[2][3][4];
    {
        const float* arow = tgt + (size_t)q * D5;   // [t(32)][z(24)]
        #pragma unroll
        for (int mi = 0; mi < 2; ++mi)
            #pragma unroll
            for (int ks = 0; ks < 3; ++ks) {
                int r = gr + 16 * mi, c = 8 * ks + gc;
                afr[mi][ks][0] = cvt_tf32(arow[r * ZD + c]);
                afr[mi][ks][1] = cvt_tf32(arow[(r + 8) * ZD + c]);
                afr[mi][ks][2] = cvt_tf32(arow[r * ZD + c + 4]);
                afr[mi][ks][3] = cvt_tf32(arow[(r + 8) * ZD + c + 4]);
            }
    }

    float* __restrict__ out0 = out + (size_t)q * NK;
    float* __restrict__ out1 = out0 + (size_t)NQ * NK;

    stage(sbuf, mem + (size_t)k0 * D5, tid);
    __syncthreads();

    for (int b = 0; b < NBATCH; ++b) {
        ull* __restrict__ cur = sbuf + (size_t)(b & 1) * BUF_F2;
        if (b + 1 < NBATCH)
            stage(sbuf + (size_t)((b + 1) & 1) * BUF_F2,
                  mem + (size_t)(k0 + (b + 1) * NB) * D5, tid);

        #pragma unroll 1
        for (int kk = 0; kk < NB; ++kk) {
            const ull* __restrict__ bb = cur + (size_t)kk * 384;

            float acc[2][4][4];
            #pragma unroll
            for (int mi = 0; mi < 2; ++mi)
                #pragma unroll
                for (int ni = 0; ni < 4; ++ni)
                    #pragma unroll
                    for (int j = 0; j < 4; ++j) acc[mi][ni][j] = 0.f;

            #pragma unroll
            for (int ks = 0; ks < 3; ++ks) {
                ull bf[4];
                #pragma unroll
                for (int ni = 0; ni < 4; ++ni)
                    bf[ni] = bb[(ks * 32 + gr + 8 * ni) * 4 + gc];   // LDS.64, conflict-free
                #pragma unroll
                for (int mi = 0; mi < 2; ++mi)
                    #pragma unroll
                    for (int ni = 0; ni < 4; ++ni)
                        mma8(acc[mi][ni], afr[mi][ks], bf[ni]);
            }

            // ---- Epilogue: rows = t, cols = s ----
            // (1) per-row max over 8 in-thread cols -> 4 row slots
            float rm[4];
            #pragma unroll
            for (int mi = 0; mi < 2; ++mi)
                #pragma unroll
                for (int h = 0; h < 2; ++h) {
                    float m = acc[mi][0][2 * h];
                    m = fmaxf(m, acc[mi][0][2 * h + 1]);
                    #pragma unroll
                    for (int ni = 1; ni < 4; ++ni) {
                        m = fmaxf(m, acc[mi][ni][2 * h]);
                        m = fmaxf(m, acc[mi][ni][2 * h + 1]);
                    }
                    rm[2 * mi + h] = m;
                }
            #pragma unroll
            for (int i = 0; i < 4; ++i) {
                rm[i] = fmaxf(rm[i], __shfl_xor_sync(0xffffffffu, rm[i], 1));
                rm[i] = fmaxf(rm[i], __shfl_xor_sync(0xffffffffu, rm[i], 2));
            }
            float tsum = (rm[0] + rm[1]) + (rm[2] + rm[3]);
            tsum += __shfl_xor_sync(0xffffffffu, tsum, 4);
            tsum += __shfl_xor_sync(0xffffffffu, tsum, 8);
            tsum += __shfl_xor_sync(0xffffffffu, tsum, 16);

            // (2) per-col max over 4 in-thread rows -> 8 col slots
            float ssum = 0.f;
            #pragma unroll
            for (int ni = 0; ni < 4; ++ni)
                #pragma unroll
                for (int p = 0; p < 2; ++p) {
                    float m = fmaxf(fmaxf(acc[0][ni][p], acc[0][ni][p + 2]),
                                    fmaxf(acc[1][ni][p], acc[1][ni][p + 2]));
                    m = fmaxf(m, __shfl_xor_sync(0xffffffffu, m, 4));
                    m = fmaxf(m, __shfl_xor_sync(0xffffffffu, m, 8));
                    m = fmaxf(m, __shfl_xor_sync(0xffffffffu, m, 16));
                    ssum += m;
                }
            ssum += __shfl_xor_sync(0xffffffffu, ssum, 1);
            ssum += __shfl_xor_sync(0xffffffffu, ssum, 2);

            float mean = (tsum + ssum) * (1.0f / 64.0f);
            float res  = 1.0f / (1.0f + __expf(-mean));
            if (lane == 0) {
                int k = k0 + b * NB + kk;
                out0[k] = res;
                out1[k] = res;
            }
        }
        __syncthreads();
    }
}

extern "C" void kernel_launch(void* const* d_in, const int* in_sizes, int n_in,
                              void* d_out, int out_size)
{
    const float* tgt = (const float*)d_in[0];   // [128, 768]
    const float* mem = (const float*)d_in[1];   // [2048, 768]
    float* out = (float*)d_out;                 // [2, 128, 2048]
    (void)in_sizes; (void)n_in; (void)out_size;

    cudaFuncSetAttribute(matcher_hmma,
                         cudaFuncAttributeMaxDynamicSharedMemorySize, SMEM_BYTES);
    matcher_hmma<<<256, NTHR, SMEM_BYTES>>>(tgt, mem, out);
}

// round 5
// speedup vs baseline: 3.6820x; 1.2183x over previous
#include <cuda_runtime.h>
#include <cstdint>

#define NQ     128
#define NK     2048
#define D5     768
#define SEQ    32
#define ZD     24
#define NTHR   256
#define KCHUNK 128
#define NB     16
#define NBATCH (KCHUNK / NB)

// per-buffer u64s: NB rows * 2 ksteps * 32 s * 4 j
#define BUF_U64 (NB * 2 * 32 * 4)          // 4096
#define SMEM_BYTES (2 * BUF_U64 * 8)       // 65536

typedef unsigned long long ull;

__device__ __forceinline__ uint32_t pk(float lo, float hi) {
    uint32_t r; asm("cvt.rn.bf16x2.f32 %0, %1, %2;" : "=r"(r) : "f"(hi), "f"(lo));
    return r;
}

// bf16 m16n8k16, zero-init accumulator (C = RZ)
__device__ __forceinline__ void mma16_z(float* c, const uint32_t* a, ull b) {
    uint32_t b0 = (uint32_t)b, b1 = (uint32_t)(b >> 32);
    asm volatile(
        "mma.sync.aligned.m16n8k16.row.col.f32.bf16.bf16.f32 "
        "{%0,%1,%2,%3}, {%4,%5,%6,%7}, {%8,%9}, {%10,%10,%10,%10};"
        : "=f"(c[0]), "=f"(c[1]), "=f"(c[2]), "=f"(c[3])
        : "r"(a[0]), "r"(a[1]), "r"(a[2]), "r"(a[3]), "r"(b0), "r"(b1), "f"(0.0f));
}
__device__ __forceinline__ void mma16(float* c, const uint32_t* a, ull b) {
    uint32_t b0 = (uint32_t)b, b1 = (uint32_t)(b >> 32);
    asm volatile(
        "mma.sync.aligned.m16n8k16.row.col.f32.bf16.bf16.f32 "
        "{%0,%1,%2,%3}, {%4,%5,%6,%7}, {%8,%9}, {%0,%1,%2,%3};"
        : "+f"(c[0]), "+f"(c[1]), "+f"(c[2]), "+f"(c[3])
        : "r"(a[0]), "r"(a[1]), "r"(a[2]), "r"(a[3]), "r"(b0), "r"(b1));
}

// Stage NB memory rows as bf16, zipped so each B fragment is one LDS.64:
//  u64[(kk*2+ks)*128 + s*4 + j] = (pair_{ks?8+j:j}, ks? 0 : pair_{j+4})
__device__ __forceinline__ void stage(ull* __restrict__ buf,
                                      const float* __restrict__ kbase, int tid) {
    #pragma unroll
    for (int i = 0; i < 2; ++i) {
        int task = tid + i * NTHR;          // 0..511
        int kk = task >> 5, s = task & 31;
        const float4* p = reinterpret_cast<const float4*>(kbase + kk * D5 + s * ZD);
        float4 x0 = p[0], x1 = p[1], x2 = p[2], x3 = p[3], x4 = p[4], x5 = p[5];
        uint32_t p0 = pk(x0.x, x0.y), p1 = pk(x0.z, x0.w);
        uint32_t p2 = pk(x1.x, x1.y), p3 = pk(x1.z, x1.w);
        uint32_t p4 = pk(x2.x, x2.y), p5 = pk(x2.z, x2.w);
        uint32_t p6 = pk(x3.x, x3.y), p7 = pk(x3.z, x3.w);
        uint32_t p8 = pk(x4.x, x4.y), p9 = pk(x4.z, x4.w);
        uint32_t pA = pk(x5.x, x5.y), pB = pk(x5.z, x5.w);
        ulonglong2* d0 = reinterpret_cast<ulonglong2*>(buf + ((size_t)(kk * 2) * 32 + s) * 4);
        d0[0] = make_ulonglong2((ull)p0 | ((ull)p4 << 32), (ull)p1 | ((ull)p5 << 32));
        d0[1] = make_ulonglong2((ull)p2 | ((ull)p6 << 32), (ull)p3 | ((ull)p7 << 32));
        ulonglong2* d1 = reinterpret_cast<ulonglong2*>(buf + ((size_t)(kk * 2 + 1) * 32 + s) * 4);
        d1[0] = make_ulonglong2((ull)p8, (ull)p9);
        d1[1] = make_ulonglong2((ull)pA, (ull)pB);
    }
}

extern __shared__ ull sbuf[];

__global__ __launch_bounds__(NTHR, 2)
void matcher_hmma(const float* __restrict__ tgt,
                  const float* __restrict__ mem,
                  float* __restrict__ out)
{
    const int tid  = threadIdx.x;
    const int warp = tid >> 5;
    const int lane = tid & 31;
    const int gr   = lane >> 2;          // 0..7
    const int gc   = lane & 3;           // 0..3

    const int q0 = (blockIdx.x >> 4) * 8;
    const int k0 = (blockIdx.x & 15) * KCHUNK;
    const int q  = q0 + warp;

    // ---- A fragments (bf16 pairs), resident for whole kernel: [mi][ks][4] ----
    uint32_t afr[2][2][4];
    {
        const float* a = tgt + (size_t)q * D5;   // [t(32)][z(24)]
        #pragma unroll
        for (int mi = 0; mi < 2; ++mi) {
            int r = gr + 16 * mi;
            const float* r0 = a + r * ZD;
            const float* r1 = a + (r + 8) * ZD;
            afr[mi][0][0] = pk(r0[2 * gc],      r0[2 * gc + 1]);
            afr[mi][0][1] = pk(r1[2 * gc],      r1[2 * gc + 1]);
            afr[mi][0][2] = pk(r0[2 * gc + 8],  r0[2 * gc + 9]);
            afr[mi][0][3] = pk(r1[2 * gc + 8],  r1[2 * gc + 9]);
            afr[mi][1][0] = pk(r0[2 * gc + 16], r0[2 * gc + 17]);
            afr[mi][1][1] = pk(r1[2 * gc + 16], r1[2 * gc + 17]);
            afr[mi][1][2] = 0u;
            afr[mi][1][3] = 0u;
        }
    }

    float* __restrict__ out0 = out + (size_t)q * NK;
    float* __restrict__ out1 = out0 + (size_t)NQ * NK;

    stage(sbuf, mem + (size_t)k0 * D5, tid);
    __syncthreads();

    const int p0b = (lane >> 2) & 1;   // gr bit0
    const int p1b = (lane >> 3) & 1;   // gr bit1
    const int p2b = (lane >> 4) & 1;   // gr bit2
    const int q0b = lane & 1;          // gc bit0
    const int q1b = (lane >> 1) & 1;   // gc bit1

    for (int b = 0; b < NBATCH; ++b) {
        ull* __restrict__ cur = sbuf + (size_t)(b & 1) * BUF_U64;
        if (b + 1 < NBATCH)
            stage(sbuf + (size_t)((b + 1) & 1) * BUF_U64,
                  mem + (size_t)(k0 + (b + 1) * NB) * D5, tid);

        #pragma unroll 1
        for (int kk = 0; kk < NB; ++kk) {
            const ull* __restrict__ bb = cur + (size_t)kk * 256;

            float acc[2][4][4];
            ull bf0[4], bf1[4];
            #pragma unroll
            for (int ni = 0; ni < 4; ++ni) {
                bf0[ni] = bb[(gr + 8 * ni) * 4 + gc];          // ks0, LDS.64 conflict-free
                bf1[ni] = bb[(32 + gr + 8 * ni) * 4 + gc];     // ks1
            }
            #pragma unroll
            for (int mi = 0; mi < 2; ++mi)
                #pragma unroll
                for (int ni = 0; ni < 4; ++ni) {
                    mma16_z(acc[mi][ni], afr[mi][0], bf0[ni]);  // C = 0 (RZ)
                    mma16(acc[mi][ni], afr[mi][1], bf1[ni]);
                }

            // ---- Pooling epilogue (rows = t, cols = s) ----
            // Row maxes: slot (mi,h) -> row gr + 8h + 16mi; in-thread over 8 cols.
            float rm[4];
            #pragma unroll
            for (int mi = 0; mi < 2; ++mi)
                #pragma unroll
                for (int h = 0; h < 2; ++h) {
                    float m = fmaxf(acc[mi][0][2 * h], acc[mi][0][2 * h + 1]);
                    #pragma unroll
                    for (int ni = 1; ni < 4; ++ni)
                        m = fmaxf(m, fmaxf(acc[mi][ni][2 * h], acc[mi][ni][2 * h + 1]));
                    rm[2 * mi + h] = m;
                }
            // Reduce-scatter rows over gc (xor 1, 2): each lane ends owning 1 row.
            float w0, w1, row_own;
            {
                float s0 = q0b ? rm[0] : rm[2], k0v = q0b ? rm[2] : rm[0];
                float s1 = q0b ? rm[1] : rm[3], k1v = q0b ? rm[3] : rm[1];
                w0 = fmaxf(k0v, __shfl_xor_sync(0xffffffffu, s0, 1));
                w1 = fmaxf(k1v, __shfl_xor_sync(0xffffffffu, s1, 1));
                float s2 = q1b ? w0 : w1, k2v = q1b ? w1 : w0;
                row_own = fmaxf(k2v, __shfl_xor_sync(0xffffffffu, s2, 2));
            }

            // Col maxes: in-thread over 4 rows -> cm[8]; reduce-scatter over gr (xor 4,8,16).
            float cm[8];
            #pragma unroll
            for (int ni = 0; ni < 4; ++ni)
                #pragma unroll
                for (int p = 0; p < 2; ++p)
                    cm[ni * 2 + p] = fmaxf(fmaxf(acc[0][ni][p], acc[0][ni][p + 2]),
                                           fmaxf(acc[1][ni][p], acc[1][ni][p + 2]));
            float v4[4];
            #pragma unroll
            for (int j = 0; j < 4; ++j) {
                float s = p0b ? cm[j] : cm[j + 4];
                float k = p0b ? cm[j + 4] : cm[j];
                v4[j] = fmaxf(k, __shfl_xor_sync(0xffffffffu, s, 4));
            }
            float v2[2];
            #pragma unroll
            for (int j = 0; j < 2; ++j) {
                float s = p1b ? v4[j] : v4[j + 2];
                float k = p1b ? v4[j + 2] : v4[j];
                v2[j] = fmaxf(k, __shfl_xor_sync(0xffffffffu, s, 8));
            }
            float col_own;
            {
                float s = p2b ? v2[0] : v2[1];
                float k = p2b ? v2[1] : v2[0];
                col_own = fmaxf(k, __shfl_xor_sync(0xffffffffu, s, 16));
            }

            // Single shared butterfly sums all 32 owned rows + 32 owned cols.
            float tot = row_own + col_own;
            #pragma unroll
            for (int o = 16; o; o >>= 1)
                tot += __shfl_xor_sync(0xffffffffu, tot, o);

            float mean = tot * (1.0f / 64.0f);
            float res  = 1.0f / (1.0f + __expf(-mean));
            if (lane == 0) {
                int k = k0 + b * NB + kk;
                out0[k] = res;
                out1[k] = res;
            }
        }
        __syncthreads();
    }
}

extern "C" void kernel_launch(void* const* d_in, const int* in_sizes, int n_in,
                              void* d_out, int out_size)
{
    const float* tgt = (const float*)d_in[0];   // [128, 768]
    const float* mem = (const float*)d_in[1];   // [2048, 768]
    float* out = (float*)d_out;                 // [2, 128, 2048]
    (void)in_sizes; (void)n_in; (void)out_size;

    cudaFuncSetAttribute(matcher_hmma,
                         cudaFuncAttributeMaxDynamicSharedMemorySize, SMEM_BYTES);
    matcher_hmma<<<256, NTHR, SMEM_BYTES>>>(tgt, mem, out);
}

// round 6
// speedup vs baseline: 3.8077x; 1.0341x over previous
#include <cuda_runtime.h>
#include <cstdint>

#define NQ     128
#define NK     2048
#define D5     768
#define SEQ    32
#define ZD     24
#define NTHR   256
#define KCHUNK 64
#define NB     8
#define NBATCH (KCHUNK / NB)

// per-buffer u64s: NB rows * 2 ksteps * 32 s * 4 j
#define BUF_U64 (NB * 2 * 32 * 4)          // 2048
#define SMEM_BYTES (2 * BUF_U64 * 8)       // 32768

typedef unsigned long long ull;

__device__ __forceinline__ uint32_t pk(float lo, float hi) {
    uint32_t r; asm("cvt.rn.bf16x2.f32 %0, %1, %2;" : "=r"(r) : "f"(hi), "f"(lo));
    return r;
}

__device__ __forceinline__ void mma16_z(float* c, const uint32_t* a, ull b) {
    uint32_t b0 = (uint32_t)b, b1 = (uint32_t)(b >> 32);
    asm volatile(
        "mma.sync.aligned.m16n8k16.row.col.f32.bf16.bf16.f32 "
        "{%0,%1,%2,%3}, {%4,%5,%6,%7}, {%8,%9}, {%10,%10,%10,%10};"
        : "=f"(c[0]), "=f"(c[1]), "=f"(c[2]), "=f"(c[3])
        : "r"(a[0]), "r"(a[1]), "r"(a[2]), "r"(a[3]), "r"(b0), "r"(b1), "f"(0.0f));
}
__device__ __forceinline__ void mma16(float* c, const uint32_t* a, ull b) {
    uint32_t b0 = (uint32_t)b, b1 = (uint32_t)(b >> 32);
    asm volatile(
        "mma.sync.aligned.m16n8k16.row.col.f32.bf16.bf16.f32 "
        "{%0,%1,%2,%3}, {%4,%5,%6,%7}, {%8,%9}, {%0,%1,%2,%3};"
        : "+f"(c[0]), "+f"(c[1]), "+f"(c[2]), "+f"(c[3])
        : "r"(a[0]), "r"(a[1]), "r"(a[2]), "r"(a[3]), "r"(b0), "r"(b1));
}

// Stage NB memory rows as bf16, zipped so each B fragment is one LDS.64.
// Exactly one task per thread (NB*32 == NTHR).
__device__ __forceinline__ void stage(ull* __restrict__ buf,
                                      const float* __restrict__ kbase, int tid) {
    int kk = tid >> 5, s = tid & 31;
    const float4* p = reinterpret_cast<const float4*>(kbase + kk * D5 + s * ZD);
    float4 x0 = p[0], x1 = p[1], x2 = p[2], x3 = p[3], x4 = p[4], x5 = p[5];
    uint32_t p0 = pk(x0.x, x0.y), p1 = pk(x0.z, x0.w);
    uint32_t p2 = pk(x1.x, x1.y), p3 = pk(x1.z, x1.w);
    uint32_t p4 = pk(x2.x, x2.y), p5 = pk(x2.z, x2.w);
    uint32_t p6 = pk(x3.x, x3.y), p7 = pk(x3.z, x3.w);
    uint32_t p8 = pk(x4.x, x4.y), p9 = pk(x4.z, x4.w);
    uint32_t pA = pk(x5.x, x5.y), pB = pk(x5.z, x5.w);
    ulonglong2* d0 = reinterpret_cast<ulonglong2*>(buf + ((size_t)(kk * 2) * 32 + s) * 4);
    d0[0] = make_ulonglong2((ull)p0 | ((ull)p4 << 32), (ull)p1 | ((ull)p5 << 32));
    d0[1] = make_ulonglong2((ull)p2 | ((ull)p6 << 32), (ull)p3 | ((ull)p7 << 32));
    ulonglong2* d1 = reinterpret_cast<ulonglong2*>(buf + ((size_t)(kk * 2 + 1) * 32 + s) * 4);
    d1[0] = make_ulonglong2((ull)p8, (ull)p9);
    d1[1] = make_ulonglong2((ull)pA, (ull)pB);
}

extern __shared__ ull sbuf[];

__global__ __launch_bounds__(NTHR, 3)
void matcher_hmma(const float* __restrict__ tgt,
                  const float* __restrict__ mem,
                  float* __restrict__ out)
{
    const int tid  = threadIdx.x;
    const int warp = tid >> 5;
    const int lane = tid & 31;
    const int gr   = lane >> 2;
    const int gc   = lane & 3;

    const int q0 = (blockIdx.x >> 5) * 8;       // 16 q-chunks
    const int k0 = (blockIdx.x & 31) * KCHUNK;  // 32 k-chunks
    const int q  = q0 + warp;

    // A fragments (bf16 pairs), resident: [mi][ks][4]
    uint32_t afr[2][2][4];
    {
        const float* a = tgt + (size_t)q * D5;
        #pragma unroll
        for (int mi = 0; mi < 2; ++mi) {
            int r = gr + 16 * mi;
            const float* r0 = a + r * ZD;
            const float* r1 = a + (r + 8) * ZD;
            afr[mi][0][0] = pk(r0[2 * gc],      r0[2 * gc + 1]);
            afr[mi][0][1] = pk(r1[2 * gc],      r1[2 * gc + 1]);
            afr[mi][0][2] = pk(r0[2 * gc + 8],  r0[2 * gc + 9]);
            afr[mi][0][3] = pk(r1[2 * gc + 8],  r1[2 * gc + 9]);
            afr[mi][1][0] = pk(r0[2 * gc + 16], r0[2 * gc + 17]);
            afr[mi][1][1] = pk(r1[2 * gc + 16], r1[2 * gc + 17]);
            afr[mi][1][2] = 0u;
            afr[mi][1][3] = 0u;
        }
    }

    float* __restrict__ out0 = out + (size_t)q * NK;
    float* __restrict__ out1 = out0 + (size_t)NQ * NK;

    stage(sbuf, mem + (size_t)k0 * D5, tid);
    __syncthreads();

    const int p0b = (lane >> 2) & 1;
    const int p1b = (lane >> 3) & 1;
    const int p2b = (lane >> 4) & 1;
    const int q0b = lane & 1;
    const int q1b = (lane >> 1) & 1;

    for (int b = 0; b < NBATCH; ++b) {
        ull* __restrict__ cur = sbuf + (size_t)(b & 1) * BUF_U64;
        if (b + 1 < NBATCH)
            stage(sbuf + (size_t)((b + 1) & 1) * BUF_U64,
                  mem + (size_t)(k0 + (b + 1) * NB) * D5, tid);

        #pragma unroll 1
        for (int kk = 0; kk < NB; ++kk) {
            const ull* __restrict__ bb = cur + (size_t)kk * 256;

            float acc[2][4][4];
            ull bf0[4], bf1[4];
            #pragma unroll
            for (int ni = 0; ni < 4; ++ni) {
                bf0[ni] = bb[(gr + 8 * ni) * 4 + gc];
                bf1[ni] = bb[(32 + gr + 8 * ni) * 4 + gc];
            }
            #pragma unroll
            for (int mi = 0; mi < 2; ++mi)
                #pragma unroll
                for (int ni = 0; ni < 4; ++ni) {
                    mma16_z(acc[mi][ni], afr[mi][0], bf0[ni]);
                    mma16(acc[mi][ni], afr[mi][1], bf1[ni]);
                }

            // ---- Pooling epilogue (rows = t, cols = s) ----
            float rm[4];
            #pragma unroll
            for (int mi = 0; mi < 2; ++mi)
                #pragma unroll
                for (int h = 0; h < 2; ++h) {
                    float m = fmaxf(acc[mi][0][2 * h], acc[mi][0][2 * h + 1]);
                    #pragma unroll
                    for (int ni = 1; ni < 4; ++ni)
                        m = fmaxf(m, fmaxf(acc[mi][ni][2 * h], acc[mi][ni][2 * h + 1]));
                    rm[2 * mi + h] = m;
                }
            float row_own;
            {
                float s0 = q0b ? rm[0] : rm[2], k0v = q0b ? rm[2] : rm[0];
                float s1 = q0b ? rm[1] : rm[3], k1v = q0b ? rm[3] : rm[1];
                float w0 = fmaxf(k0v, __shfl_xor_sync(0xffffffffu, s0, 1));
                float w1 = fmaxf(k1v, __shfl_xor_sync(0xffffffffu, s1, 1));
                float s2 = q1b ? w0 : w1, k2v = q1b ? w1 : w0;
                row_own = fmaxf(k2v, __shfl_xor_sync(0xffffffffu, s2, 2));
            }

            float cm[8];
            #pragma unroll
            for (int ni = 0; ni < 4; ++ni)
                #pragma unroll
                for (int p = 0; p < 2; ++p)
                    cm[ni * 2 + p] = fmaxf(fmaxf(acc[0][ni][p], acc[0][ni][p + 2]),
                                           fmaxf(acc[1][ni][p], acc[1][ni][p + 2]));
            float v4[4];
            #pragma unroll
            for (int j = 0; j < 4; ++j) {
                float s = p0b ? cm[j] : cm[j + 4];
                float k = p0b ? cm[j + 4] : cm[j];
                v4[j] = fmaxf(k, __shfl_xor_sync(0xffffffffu, s, 4));
            }
            float v2[2];
            #pragma unroll
            for (int j = 0; j < 2; ++j) {
                float s = p1b ? v4[j] : v4[j + 2];
                float k = p1b ? v4[j + 2] : v4[j];
                v2[j] = fmaxf(k, __shfl_xor_sync(0xffffffffu, s, 8));
            }
            float col_own;
            {
                float s = p2b ? v2[0] : v2[1];
                float k = p2b ? v2[1] : v2[0];
                col_own = fmaxf(k, __shfl_xor_sync(0xffffffffu, s, 16));
            }

            float tot = row_own + col_own;
            #pragma unroll
            for (int o = 16; o; o >>= 1)
                tot += __shfl_xor_sync(0xffffffffu, tot, o);

            float res = 1.0f / (1.0f + __expf(tot * -0.015625f));
            if (lane == 0) {
                int k = k0 + b * NB + kk;
                out0[k] = res;
                out1[k] = res;
            }
        }
        __syncthreads();
    }
}

extern "C" void kernel_launch(void* const* d_in, const int* in_sizes, int n_in,
                              void* d_out, int out_size)
{
    const float* tgt = (const float*)d_in[0];   // [128, 768]
    const float* mem = (const float*)d_in[1];   // [2048, 768]
    float* out = (float*)d_out;                 // [2, 128, 2048]
    (void)in_sizes; (void)n_in; (void)out_size;

    cudaFuncSetAttribute(matcher_hmma,
                         cudaFuncAttributeMaxDynamicSharedMemorySize, SMEM_BYTES);
    matcher_hmma<<<512, NTHR, SMEM_BYTES>>>(tgt, mem, out);
}

// round 7
// speedup vs baseline: 3.8336x; 1.0068x over previous
#include <cuda_runtime.h>
#include <cstdint>

#define NQ     128
#define NK     2048
#define D5     768
#define SEQ    32
#define ZD     24
#define NTHR   256
#define KCHUNK 64
#define NB     8
#define NBATCH (KCHUNK / NB)

// per-buffer u64s: NB rows * 2 ksteps * 32 s * 4 j
#define BUF_U64 (NB * 2 * 32 * 4)          // 2048
#define SMEM_BYTES (2 * BUF_U64 * 8)       // 32768

typedef unsigned long long ull;

__device__ __forceinline__ uint32_t pk(float lo, float hi) {
    uint32_t r; asm("cvt.rn.bf16x2.f32 %0, %1, %2;" : "=r"(r) : "f"(hi), "f"(lo));
    return r;
}

__device__ __forceinline__ void mma16_z(float* c, const uint32_t* a, ull b) {
    uint32_t b0 = (uint32_t)b, b1 = (uint32_t)(b >> 32);
    asm volatile(
        "mma.sync.aligned.m16n8k16.row.col.f32.bf16.bf16.f32 "
        "{%0,%1,%2,%3}, {%4,%5,%6,%7}, {%8,%9}, {%10,%10,%10,%10};"
        : "=f"(c[0]), "=f"(c[1]), "=f"(c[2]), "=f"(c[3])
        : "r"(a[0]), "r"(a[1]), "r"(a[2]), "r"(a[3]), "r"(b0), "r"(b1), "f"(0.0f));
}
__device__ __forceinline__ void mma16(float* c, const uint32_t* a, ull b) {
    uint32_t b0 = (uint32_t)b, b1 = (uint32_t)(b >> 32);
    asm volatile(
        "mma.sync.aligned.m16n8k16.row.col.f32.bf16.bf16.f32 "
        "{%0,%1,%2,%3}, {%4,%5,%6,%7}, {%8,%9}, {%0,%1,%2,%3};"
        : "+f"(c[0]), "+f"(c[1]), "+f"(c[2]), "+f"(c[3])
        : "r"(a[0]), "r"(a[1]), "r"(a[2]), "r"(a[3]), "r"(b0), "r"(b1));
}

// Stage NB memory rows as bf16, zipped so each B fragment is one LDS.64.
// Exactly one task per thread (NB*32 == NTHR).
__device__ __forceinline__ void stage(ull* __restrict__ buf,
                                      const float* __restrict__ kbase, int tid) {
    int kk = tid >> 5, s = tid & 31;
    const float4* p = reinterpret_cast<const float4*>(kbase + kk * D5 + s * ZD);
    float4 x0 = p[0], x1 = p[1], x2 = p[2], x3 = p[3], x4 = p[4], x5 = p[5];
    uint32_t p0 = pk(x0.x, x0.y), p1 = pk(x0.z, x0.w);
    uint32_t p2 = pk(x1.x, x1.y), p3 = pk(x1.z, x1.w);
    uint32_t p4 = pk(x2.x, x2.y), p5 = pk(x2.z, x2.w);
    uint32_t p6 = pk(x3.x, x3.y), p7 = pk(x3.z, x3.w);
    uint32_t p8 = pk(x4.x, x4.y), p9 = pk(x4.z, x4.w);
    uint32_t pA = pk(x5.x, x5.y), pB = pk(x5.z, x5.w);
    ulonglong2* d0 = reinterpret_cast<ulonglong2*>(buf + ((size_t)(kk * 2) * 32 + s) * 4);
    d0[0] = make_ulonglong2((ull)p0 | ((ull)p4 << 32), (ull)p1 | ((ull)p5 << 32));
    d0[1] = make_ulonglong2((ull)p2 | ((ull)p6 << 32), (ull)p3 | ((ull)p7 << 32));
    ulonglong2* d1 = reinterpret_cast<ulonglong2*>(buf + ((size_t)(kk * 2 + 1) * 32 + s) * 4);
    d1[0] = make_ulonglong2((ull)p8, (ull)p9);
    d1[1] = make_ulonglong2((ull)pA, (ull)pB);
}

extern __shared__ ull sbuf[];

__global__ __launch_bounds__(NTHR, 2)
void matcher_hmma(const float* __restrict__ tgt,
                  const float* __restrict__ mem,
                  float* __restrict__ out)
{
    const int tid  = threadIdx.x;
    const int warp = tid >> 5;
    const int lane = tid & 31;
    const int gr   = lane >> 2;
    const int gc   = lane & 3;

    const int q0 = (blockIdx.x >> 5) * 8;       // 16 q-chunks
    const int k0 = (blockIdx.x & 31) * KCHUNK;  // 32 k-chunks
    const int q  = q0 + warp;

    // A fragments (bf16 pairs), resident: [mi][ks][4]
    uint32_t afr[2][2][4];
    {
        const float* a = tgt + (size_t)q * D5;
        #pragma unroll
        for (int mi = 0; mi < 2; ++mi) {
            int r = gr + 16 * mi;
            const float* r0 = a + r * ZD;
            const float* r1 = a + (r + 8) * ZD;
            afr[mi][0][0] = pk(r0[2 * gc],      r0[2 * gc + 1]);
            afr[mi][0][1] = pk(r1[2 * gc],      r1[2 * gc + 1]);
            afr[mi][0][2] = pk(r0[2 * gc + 8],  r0[2 * gc + 9]);
            afr[mi][0][3] = pk(r1[2 * gc + 8],  r1[2 * gc + 9]);
            afr[mi][1][0] = pk(r0[2 * gc + 16], r0[2 * gc + 17]);
            afr[mi][1][1] = pk(r1[2 * gc + 16], r1[2 * gc + 17]);
            afr[mi][1][2] = 0u;
            afr[mi][1][3] = 0u;
        }
    }

    float* __restrict__ out0 = out + (size_t)q * NK;
    float* __restrict__ out1 = out0 + (size_t)NQ * NK;

    stage(sbuf, mem + (size_t)k0 * D5, tid);
    __syncthreads();

    const int p0b = (lane >> 2) & 1;
    const int p1b = (lane >> 3) & 1;
    const int p2b = (lane >> 4) & 1;
    const int q0b = lane & 1;
    const int q1b = (lane >> 1) & 1;

    for (int b = 0; b < NBATCH; ++b) {
        ull* __restrict__ cur = sbuf + (size_t)(b & 1) * BUF_U64;
        if (b + 1 < NBATCH)
            stage(sbuf + (size_t)((b + 1) & 1) * BUF_U64,
                  mem + (size_t)(k0 + (b + 1) * NB) * D5, tid);

        #pragma unroll 1
        for (int kk = 0; kk < NB; kk += 2) {
            // ---- Phase 1: MMAs + in-thread max extraction, pairs u=0,1 sequential ----
            float rm[2][4], cm[2][8];
            #pragma unroll
            for (int u = 0; u < 2; ++u) {
                const ull* __restrict__ bb = cur + (size_t)(kk + u) * 256;
                ull bf0[4], bf1[4];
                #pragma unroll
                for (int ni = 0; ni < 4; ++ni) {
                    bf0[ni] = bb[(gr + 8 * ni) * 4 + gc];
                    bf1[ni] = bb[(32 + gr + 8 * ni) * 4 + gc];
                }
                float acc[2][4][4];
                #pragma unroll
                for (int mi = 0; mi < 2; ++mi)
                    #pragma unroll
                    for (int ni = 0; ni < 4; ++ni) {
                        mma16_z(acc[mi][ni], afr[mi][0], bf0[ni]);
                        mma16(acc[mi][ni], afr[mi][1], bf1[ni]);
                    }
                // Row maxes (over 8 in-thread cols), slots (mi,h)
                #pragma unroll
                for (int mi = 0; mi < 2; ++mi)
                    #pragma unroll
                    for (int h = 0; h < 2; ++h) {
                        float m = fmaxf(acc[mi][0][2 * h], acc[mi][0][2 * h + 1]);
                        #pragma unroll
                        for (int ni = 1; ni < 4; ++ni)
                            m = fmaxf(m, fmaxf(acc[mi][ni][2 * h], acc[mi][ni][2 * h + 1]));
                        rm[u][2 * mi + h] = m;
                    }
                // Col maxes (over 4 in-thread rows), slots (ni,p)
                #pragma unroll
                for (int ni = 0; ni < 4; ++ni)
                    #pragma unroll
                    for (int p = 0; p < 2; ++p)
                        cm[u][ni * 2 + p] = fmaxf(fmaxf(acc[0][ni][p], acc[0][ni][p + 2]),
                                                  fmaxf(acc[1][ni][p], acc[1][ni][p + 2]));
            }

            // ---- Phase 2: cross-lane reductions, u=0/1 interleaved per stage ----
            float row_own[2], col_own[2];

            // Row reduce-scatter over gc bits (xor 1, then 2)
            {
                float w0[2], w1[2];
                #pragma unroll
                for (int u = 0; u < 2; ++u) {
                    float s0 = q0b ? rm[u][0] : rm[u][2], k0v = q0b ? rm[u][2] : rm[u][0];
                    float s1 = q0b ? rm[u][1] : rm[u][3], k1v = q0b ? rm[u][3] : rm[u][1];
                    w0[u] = fmaxf(k0v, __shfl_xor_sync(0xffffffffu, s0, 1));
                    w1[u] = fmaxf(k1v, __shfl_xor_sync(0xffffffffu, s1, 1));
                }
                #pragma unroll
                for (int u = 0; u < 2; ++u) {
                    float s2 = q1b ? w0[u] : w1[u], k2v = q1b ? w1[u] : w0[u];
                    row_own[u] = fmaxf(k2v, __shfl_xor_sync(0xffffffffu, s2, 2));
                }
            }

            // Col reduce-scatter over gr bits (xor 4, 8, 16)
            {
                float v4[2][4];
                #pragma unroll
                for (int u = 0; u < 2; ++u)
                    #pragma unroll
                    for (int j = 0; j < 4; ++j) {
                        float s = p0b ? cm[u][j] : cm[u][j + 4];
                        float k = p0b ? cm[u][j + 4] : cm[u][j];
                        v4[u][j] = fmaxf(k, __shfl_xor_sync(0xffffffffu, s, 4));
                    }
                float v2[2][2];
                #pragma unroll
                for (int u = 0; u < 2; ++u)
                    #pragma unroll
                    for (int j = 0; j < 2; ++j) {
                        float s = p1b ? v4[u][j] : v4[u][j + 2];
                        float k = p1b ? v4[u][j + 2] : v4[u][j];
                        v2[u][j] = fmaxf(k, __shfl_xor_sync(0xffffffffu, s, 8));
                    }
                #pragma unroll
                for (int u = 0; u < 2; ++u) {
                    float s = p2b ? v2[u][0] : v2[u][1];
                    float k = p2b ? v2[u][1] : v2[u][0];
                    col_own[u] = fmaxf(k, __shfl_xor_sync(0xffffffffu, s, 16));
                }
            }

            // Final butterflies, interleaved
            float tot0 = row_own[0] + col_own[0];
            float tot1 = row_own[1] + col_own[1];
            #pragma unroll
            for (int o = 16; o; o >>= 1) {
                tot0 += __shfl_xor_sync(0xffffffffu, tot0, o);
                tot1 += __shfl_xor_sync(0xffffffffu, tot1, o);
            }

            float res0 = 1.0f / (1.0f + __expf(tot0 * -0.015625f));
            float res1 = 1.0f / (1.0f + __expf(tot1 * -0.015625f));
            if (lane == 0) {
                int k = k0 + b * NB + kk;
                out0[k]     = res0;
                out0[k + 1] = res1;
                out1[k]     = res0;
                out1[k + 1] = res1;
            }
        }
        __syncthreads();
    }
}

extern "C" void kernel_launch(void* const* d_in, const int* in_sizes, int n_in,
                              void* d_out, int out_size)
{
    const float* tgt = (const float*)d_in[0];   // [128, 768]
    const float* mem = (const float*)d_in[1];   // [2048, 768]
    float* out = (float*)d_out;                 // [2, 128, 2048]
    (void)in_sizes; (void)n_in; (void)out_size;

    cudaFuncSetAttribute(matcher_hmma,
                         cudaFuncAttributeMaxDynamicSharedMemorySize, SMEM_BYTES);
    matcher_hmma<<<512, NTHR, SMEM_BYTES>>>(tgt, mem, out);
}